// round 9
// baseline (speedup 1.0000x reference)
#include <cuda_runtime.h>
#include <cuda_bf16.h>
#include <cstdint>

typedef unsigned long long ull;

#define TN      128
#define THREADS 512
#define CC      128
#define KD      32

// float/uint32 slot offsets in dynamic smem
#define XF_F    0                       // x fp32 [128][132]
#define XH_F    16896                   // X hi bf16-pairs uint32 [128][68]; H hi overlays after GEMM1
#define XL_F    25600                   // X lo ; H lo overlays
#define W1H_F   34304                   // W1^T hi pairs [128c][68]; ss overlays after GEMM1
#define W1L_F   43008
#define W2H_F   51712                   // W2^T hi pairs [32k][68]
#define W2L_F   53888
#define SS_F    34304                   // logits/s fp32 [128][36] (overlays W1H)
#define B1_F    56064
#define B2_F    56192
#define IB_I    56224
#define SMEM_FLOATS 56352
#define SMEM_BYTES  (SMEM_FLOATS * 4)   // 225408

#define ZERO_N4 ((64 * KD * CC) / 4)    // 65536 float4 of pooled output
#define PREP_N  (CC * 68 + KD * 68)     // 10880 prep items

__device__ uint32_t g_W1hl[2 * CC * 68];   // [hi 8704 | lo 8704], pitch-68 rows
__device__ uint32_t g_W2hl[2 * KD * 68];   // [hi 2176 | lo 2176]

// ---------- helpers ----------
static __device__ __forceinline__ ull pk2(float lo, float hi) {
    ull r; asm("mov.b64 %0,{%1,%2};" : "=l"(r) : "f"(lo), "f"(hi)); return r;
}
static __device__ __forceinline__ float2 upk2(ull v) {
    float2 f; asm("mov.b64 {%0,%1},%2;" : "=f"(f.x), "=f"(f.y) : "l"(v)); return f;
}
static __device__ __forceinline__ ull ffma2_(ull a, ull b, ull c) {
    ull d; asm("fma.rn.f32x2 %0,%1,%2,%3;" : "=l"(d) : "l"(a), "l"(b), "l"(c)); return d;
}
static __device__ __forceinline__ void split_pack(float a, float b, uint32_t& h, uint32_t& l) {
    __nv_bfloat162 th = __floats2bfloat162_rn(a, b);
    uint32_t hp = *(uint32_t*)&th;
    float ha = __uint_as_float(hp << 16);
    float hb = __uint_as_float(hp & 0xFFFF0000u);
    __nv_bfloat162 tl = __floats2bfloat162_rn(a - ha, b - hb);
    h = hp;
    l = *(uint32_t*)&tl;
}
static __device__ __forceinline__ void mma_bf16(float* d, const uint32_t* a,
                                                uint32_t b0, uint32_t b1) {
    asm volatile(
        "mma.sync.aligned.m16n8k16.row.col.f32.bf16.bf16.f32 "
        "{%0,%1,%2,%3}, {%4,%5,%6,%7}, {%8,%9}, {%0,%1,%2,%3};"
        : "+f"(d[0]), "+f"(d[1]), "+f"(d[2]), "+f"(d[3])
        : "r"(a[0]), "r"(a[1]), "r"(a[2]), "r"(a[3]), "r"(b0), "r"(b1));
}

// fused: zero pooled output + pre-split weights into bf16 hi/lo pair tiles
__global__ void hp_pre_kernel(float4* __restrict__ o,
                              const float* __restrict__ W1, const float* __restrict__ W2) {
    int idx = blockIdx.x * blockDim.x + threadIdx.x;
    if (idx < ZERO_N4) {
        o[idx] = make_float4(0.f, 0.f, 0.f, 0.f);
    } else if (idx < ZERO_N4 + PREP_N) {
        int i = idx - ZERO_N4;
        if (i < CC * 68) {
            int c = i / 68, p = i % 68;
            uint32_t h = 0, l = 0;
            if (p < 64) {
                float v0 = W1[(2 * p) * CC + c];
                float v1 = W1[(2 * p + 1) * CC + c];
                split_pack(v0, v1, h, l);
            }
            g_W1hl[i] = h;
            g_W1hl[CC * 68 + i] = l;
        } else {
            int j = i - CC * 68;
            int k = j / 68, p = j % 68;
            uint32_t h = 0, l = 0;
            if (p < 64) {
                float v0 = W2[(2 * p) * KD + k];
                float v1 = W2[(2 * p + 1) * KD + k];
                split_pack(v0, v1, h, l);
            }
            g_W2hl[j] = h;
            g_W2hl[KD * 68 + j] = l;
        }
    }
}

__global__ __launch_bounds__(THREADS, 1)
void hp_main_kernel(const float* __restrict__ x, const int* __restrict__ batch,
                    const float* __restrict__ b1, const float* __restrict__ b2,
                    float* __restrict__ out, float* __restrict__ s_out, int N)
{
    extern __shared__ __align__(16) float smem[];
    float4*   xn4 = (float4*)(smem + XF_F);        // pitch 33
    uint32_t* XH  = (uint32_t*)(smem + XH_F);      // pitch 68 (also H hi)
    uint32_t* XL  = (uint32_t*)(smem + XL_F);      // pitch 68 (also H lo)
    uint32_t* W1H = (uint32_t*)(smem + W1H_F);     // pitch 68
    uint32_t* W1L = (uint32_t*)(smem + W1L_F);
    uint32_t* W2H = (uint32_t*)(smem + W2H_F);     // pitch 68
    uint32_t* W2L = (uint32_t*)(smem + W2L_F);
    float*    ss  = smem + SS_F;                   // pitch 36
    float*    b1s = smem + B1_F;
    float*    b2s = smem + B2_F;
    int*      ib  = (int*)(smem + IB_I);

    const int tid  = threadIdx.x;
    const int lane = tid & 31;
    const int wid  = tid >> 5;          // 0..15
    const int qr   = lane >> 2;         // 0..7
    const int qc   = lane & 3;          // 0..3
    const int n0   = blockIdx.x * TN;
    const int nvalid = min(TN, N - n0);

    // ================= staging =================
    if (tid < TN) ib[tid] = (n0 + tid < N) ? batch[n0 + tid] : -1;
    if (tid < CC) b1s[tid] = b1[tid];
    if (tid < KD) b2s[tid] = b2[tid];
    {
        const float4* xg = (const float4*)x;
        #pragma unroll
        for (int it = 0; it < (TN * 32) / THREADS; ++it) {   // 8
            int idx = it * THREADS + tid;
            int n = idx >> 5, g = idx & 31;
            float4 v = make_float4(0.f, 0.f, 0.f, 0.f);
            if (n < nvalid) v = xg[(size_t)(n0 + n) * 32 + g];
            xn4[n * 33 + g] = v;
            uint32_t h0, l0, h1, l1;
            split_pack(v.x, v.y, h0, l0);
            split_pack(v.z, v.w, h1, l1);
            XH[n * 68 + 2 * g]     = h0;
            XH[n * 68 + 2 * g + 1] = h1;
            XL[n * 68 + 2 * g]     = l0;
            XL[n * 68 + 2 * g + 1] = l1;
        }
        const float4* s1 = (const float4*)g_W1hl;        // 4352 f4
        float4* d1 = (float4*)W1H;                       // W1H|W1L contiguous
        for (int i = tid; i < 2 * CC * 68 / 4; i += THREADS) d1[i] = s1[i];
        for (int i = tid; i < 2 * KD * 68; i += THREADS) W2H[i] = g_W2hl[i];
    }
    __syncthreads();

    // ===== GEMM1: H = relu(X @ W1 + b1)  3-pass bf16 mma.m16n8k16 =====
    // 16 warps = 4 m-groups x 4 n-groups; warp tile 32 rows x 32 cols
    const int mbase = (wid >> 2) * 32;
    const int cbase = (wid & 3) * 32;
    float acc[2][4][4];
    {
        #pragma unroll
        for (int mt = 0; mt < 2; ++mt)
            #pragma unroll
            for (int nt = 0; nt < 4; ++nt)
                #pragma unroll
                for (int e = 0; e < 4; ++e) acc[mt][nt][e] = 0.f;

        for (int ks = 0; ks < 8; ++ks) {
            const int kb2 = ks * 8;
            uint32_t ah[2][4], al[2][4];
            #pragma unroll
            for (int mt = 0; mt < 2; ++mt) {
                int r0 = mbase + mt * 16 + qr;
                ah[mt][0] = XH[r0 * 68 + kb2 + qc];
                ah[mt][1] = XH[(r0 + 8) * 68 + kb2 + qc];
                ah[mt][2] = XH[r0 * 68 + kb2 + 4 + qc];
                ah[mt][3] = XH[(r0 + 8) * 68 + kb2 + 4 + qc];
                al[mt][0] = XL[r0 * 68 + kb2 + qc];
                al[mt][1] = XL[(r0 + 8) * 68 + kb2 + qc];
                al[mt][2] = XL[r0 * 68 + kb2 + 4 + qc];
                al[mt][3] = XL[(r0 + 8) * 68 + kb2 + 4 + qc];
            }
            #pragma unroll
            for (int nt = 0; nt < 4; ++nt) {
                int cb = cbase + nt * 8 + qr;
                uint32_t bh0 = W1H[cb * 68 + kb2 + qc];
                uint32_t bh1 = W1H[cb * 68 + kb2 + 4 + qc];
                uint32_t bl0 = W1L[cb * 68 + kb2 + qc];
                uint32_t bl1 = W1L[cb * 68 + kb2 + 4 + qc];
                #pragma unroll
                for (int mt = 0; mt < 2; ++mt) {
                    mma_bf16(acc[mt][nt], ah[mt], bh0, bh1);
                    mma_bf16(acc[mt][nt], al[mt], bh0, bh1);
                    mma_bf16(acc[mt][nt], ah[mt], bl0, bl1);
                }
            }
        }
    }
    __syncthreads();   // all reads of X/W1 tiles done before overlays

    // ---- epilogue 1: relu + bias, write H hi/lo pairs (overlay XH/XL) ----
    {
        #pragma unroll
        for (int mt = 0; mt < 2; ++mt) {
            int r0 = mbase + mt * 16 + qr;
            #pragma unroll
            for (int nt = 0; nt < 4; ++nt) {
                int cb = cbase + nt * 8 + 2 * qc;
                int pidx = (cbase >> 1) + nt * 4 + qc;
                float v0 = fmaxf(acc[mt][nt][0] + b1s[cb], 0.f);
                float v1 = fmaxf(acc[mt][nt][1] + b1s[cb + 1], 0.f);
                float v2 = fmaxf(acc[mt][nt][2] + b1s[cb], 0.f);
                float v3 = fmaxf(acc[mt][nt][3] + b1s[cb + 1], 0.f);
                uint32_t h, l;
                split_pack(v0, v1, h, l);
                XH[r0 * 68 + pidx] = h;
                XL[r0 * 68 + pidx] = l;
                split_pack(v2, v3, h, l);
                XH[(r0 + 8) * 68 + pidx] = h;
                XL[(r0 + 8) * 68 + pidx] = l;
            }
        }
    }
    __syncthreads();

    // ===== GEMM2: logits = H @ W2 + b2 (warp = m16 tile x 2 n-tiles) =====
    {
        const int r0  = (wid >> 1) * 16 + qr;
        const int ntb = (wid & 1) * 2;
        float a2[2][4];
        #pragma unroll
        for (int nt = 0; nt < 2; ++nt)
            #pragma unroll
            for (int e = 0; e < 4; ++e) a2[nt][e] = 0.f;

        for (int js = 0; js < 8; ++js) {
            const int jb2 = js * 8;
            uint32_t ah[4], al[4];
            ah[0] = XH[r0 * 68 + jb2 + qc];
            ah[1] = XH[(r0 + 8) * 68 + jb2 + qc];
            ah[2] = XH[r0 * 68 + jb2 + 4 + qc];
            ah[3] = XH[(r0 + 8) * 68 + jb2 + 4 + qc];
            al[0] = XL[r0 * 68 + jb2 + qc];
            al[1] = XL[(r0 + 8) * 68 + jb2 + qc];
            al[2] = XL[r0 * 68 + jb2 + 4 + qc];
            al[3] = XL[(r0 + 8) * 68 + jb2 + 4 + qc];
            #pragma unroll
            for (int nt = 0; nt < 2; ++nt) {
                int kb = (ntb + nt) * 8 + qr;
                uint32_t bh0 = W2H[kb * 68 + jb2 + qc];
                uint32_t bh1 = W2H[kb * 68 + jb2 + 4 + qc];
                uint32_t bl0 = W2L[kb * 68 + jb2 + qc];
                uint32_t bl1 = W2L[kb * 68 + jb2 + 4 + qc];
                mma_bf16(a2[nt], ah, bh0, bh1);
                mma_bf16(a2[nt], al, bh0, bh1);
                mma_bf16(a2[nt], ah, bl0, bl1);
            }
        }
        #pragma unroll
        for (int nt = 0; nt < 2; ++nt) {
            int kb = (ntb + nt) * 8 + 2 * qc;
            *(float2*)&ss[r0 * 36 + kb] =
                make_float2(a2[nt][0] + b2s[kb], a2[nt][1] + b2s[kb + 1]);
            *(float2*)&ss[(r0 + 8) * 36 + kb] =
                make_float2(a2[nt][2] + b2s[kb], a2[nt][3] + b2s[kb + 1]);
        }
    }
    __syncthreads();

    // ===== softmax per node (16 warps x 8 nodes, lane = k) =====
    {
        #pragma unroll
        for (int i = 0; i < 8; ++i) {
            int n = wid * 8 + i;
            float v = ss[n * 36 + lane];
            float m = v;
            #pragma unroll
            for (int o = 16; o > 0; o >>= 1) m = fmaxf(m, __shfl_xor_sync(0xffffffffu, m, o));
            float e = __expf(v - m);
            float sum = e;
            #pragma unroll
            for (int o = 16; o > 0; o >>= 1) sum += __shfl_xor_sync(0xffffffffu, sum, o);
            float sv = e / sum;
            ss[n * 36 + lane] = sv;
            if (n < nvalid) s_out[(size_t)(n0 + n) * KD + lane] = sv;
        }
    }
    __syncthreads();

    // ===== stage 4: out[b][k][c] += sum_n s[n][k] * x[n][c]  (scalar f32x2) =====
    // 16 warps = 4 k-groups (8 k) x 4 c-groups (32 c); lane: 2 k x 4 c
    {
        const int cl = lane & 7;
        const int kq = lane >> 3;
        const int kh = (wid >> 2) * 8;
        const int cq = (wid & 3) * 32;
        const int c0 = cq + cl * 4;
        const int k0 = kh + kq * 2;

        int bmin = ib[0];
        int bmax = ib[nvalid - 1];
        for (int b = bmin; b <= bmax; ++b) {
            ull acc4[2][2];
            acc4[0][0] = acc4[0][1] = acc4[1][0] = acc4[1][1] = 0ull;
            for (int n = 0; n < TN; ++n) {
                if (ib[n] != b) continue;        // uniform across block
                float2 sA = *(const float2*)&ss[n * 36 + k0];
                float4 xv = xn4[n * 33 + (c0 >> 2)];
                ull xp0 = pk2(xv.x, xv.y);
                ull xp1 = pk2(xv.z, xv.w);
                ull sp0 = pk2(sA.x, sA.x);
                ull sp1 = pk2(sA.y, sA.y);
                acc4[0][0] = ffma2_(sp0, xp0, acc4[0][0]);
                acc4[0][1] = ffma2_(sp0, xp1, acc4[0][1]);
                acc4[1][0] = ffma2_(sp1, xp0, acc4[1][0]);
                acc4[1][1] = ffma2_(sp1, xp1, acc4[1][1]);
            }
            float* ob = out + (size_t)b * (KD * CC);
            #pragma unroll
            for (int kk = 0; kk < 2; ++kk) {
                float2 f0 = upk2(acc4[kk][0]);
                float2 f1 = upk2(acc4[kk][1]);
                float* p = &ob[(k0 + kk) * CC + c0];
                atomicAdd(p + 0, f0.x);
                atomicAdd(p + 1, f0.y);
                atomicAdd(p + 2, f1.x);
                atomicAdd(p + 3, f1.y);
            }
        }
    }
}

extern "C" void kernel_launch(void* const* d_in, const int* in_sizes, int n_in,
                              void* d_out, int out_size)
{
    const float* x     = (const float*)d_in[0];
    const int*   batch = (const int*)d_in[1];
    const float* W1    = (const float*)d_in[2];
    const float* b1    = (const float*)d_in[3];
    const float* W2    = (const float*)d_in[4];
    const float* b2    = (const float*)d_in[5];

    const int N = in_sizes[1];
    float* out = (float*)d_out;
    size_t out_elems = (size_t)out_size - (size_t)N * KD;   // B*K*C
    float* s_out = out + out_elems;

    {   // fused zero + weight prep (one launch)
        int total = ZERO_N4 + PREP_N;
        hp_pre_kernel<<<(total + 255) / 256, 256>>>((float4*)out, W1, W2);
    }

    cudaFuncSetAttribute(hp_main_kernel,
                         cudaFuncAttributeMaxDynamicSharedMemorySize, SMEM_BYTES);
    int nb = (N + TN - 1) / TN;
    hp_main_kernel<<<nb, THREADS, SMEM_BYTES>>>(x, batch, b1, b2, out, s_out, N);
}